// round 1
// baseline (speedup 1.0000x reference)
#include <cuda_runtime.h>
#include <math.h>

#define TT 8
#define HH 64
#define WWD 64
#define CC 64
#define HWX (HH*WWD)            // 4096
#define PLANE (TT*HH*WWD)       // 32768
#define KTAP 27
#define KTOT (CC*KTAP)          // 1728

// -------- device scratch (no allocs allowed) --------
__device__ float g_y1[CC*PLANE];          // lrelu(conv1) output
__device__ float g_off[54*PLANE];         // offsets
__device__ float g_W1t[KTOT*64];          // transposed weights [kidx][o]
__device__ float g_Wofft[KTOT*64];
__device__ float g_Wdt[KTOT*64];
__device__ float g_Wrt[64*64];            // [c][o]

// -------- weight transpose / pad --------
__global__ void prep_weights(const float* __restrict__ W1, const float* __restrict__ Woff,
                             const float* __restrict__ Wd, const float* __restrict__ Wr) {
    int i = blockIdx.x*256 + threadIdx.x;
    if (i < KTOT*64) {
        int kidx = i >> 6, o = i & 63;
        g_W1t[i]  = W1[o*KTOT + kidx];
        g_Wdt[i]  = Wd[o*KTOT + kidx];
        g_Wofft[i] = (o < 54) ? Woff[o*KTOT + kidx] : 0.f;
        if (i < 64*64) {
            int c = i >> 6, oo = i & 63;
            g_Wrt[i] = Wr[oo*64 + c];
        }
    }
}

// -------- generic 3x3x3 conv as implicit GEMM --------
// block: one (t,h) row of 64 w's; M=64 out channels; K=1728
__global__ void __launch_bounds__(256)
conv3x3x3_kernel(const float* __restrict__ src, const float* __restrict__ Wt,
                 const float* __restrict__ bias, float* __restrict__ dst,
                 int oc_count, int do_lrelu)
{
    __shared__ float sA[8][64];
    __shared__ float sB[8][64];
    __shared__ unsigned short sDec[KTOT];   // (c<<5)|k

    int tid = threadIdx.x;
    int t = blockIdx.x >> 6;
    int h = blockIdx.x & 63;

    for (int e = tid; e < KTOT; e += 256) {
        int c = e / 27;
        int k = e - c*27;
        sDec[e] = (unsigned short)((c<<5) | k);
    }
    __syncthreads();

    int tx = tid & 15, ty = tid >> 4;
    float acc[4][4];
    #pragma unroll
    for (int i=0;i<4;i++)
        #pragma unroll
        for (int j=0;j<4;j++) acc[i][j]=0.f;

    for (int kk = 0; kk < KTOT; kk += 8) {
        // stage A: weights [kc][o]
        #pragma unroll
        for (int i = 0; i < 2; i++) {
            int e = tid + i*256;
            int kc = e >> 6, o = e & 63;
            sA[kc][o] = Wt[(kk+kc)*64 + o];
        }
        // stage B: im2col [kc][w]
        #pragma unroll
        for (int i = 0; i < 2; i++) {
            int e = tid + i*256;
            int kc = e >> 6, w = e & 63;
            unsigned int d = sDec[kk+kc];
            int c = d >> 5;
            int k = d & 31;
            int kt = k / 9; int r = k - kt*9;
            int kh = r / 3; int kw = r - kh*3;
            int t_in = t - 1 + kt;
            int h_in = h - 1 + kh;
            int w_in = w - 1 + kw;
            float v = 0.f;
            if ((unsigned)t_in < TT && (unsigned)h_in < HH && (unsigned)w_in < WWD)
                v = src[c*PLANE + t_in*HWX + h_in*WWD + w_in];
            sB[kc][w] = v;
        }
        __syncthreads();
        #pragma unroll
        for (int kc = 0; kc < 8; kc++) {
            float4 a = *(const float4*)&sA[kc][ty*4];
            float4 b = *(const float4*)&sB[kc][tx*4];
            float av[4] = {a.x,a.y,a.z,a.w};
            float bv[4] = {b.x,b.y,b.z,b.w};
            #pragma unroll
            for (int i=0;i<4;i++)
                #pragma unroll
                for (int j=0;j<4;j++)
                    acc[i][j] = fmaf(av[i], bv[j], acc[i][j]);
        }
        __syncthreads();
    }

    int base = t*HWX + h*WWD + tx*4;
    #pragma unroll
    for (int i=0;i<4;i++) {
        int o = ty*4 + i;
        if (o < oc_count) {
            float bv = bias[o];
            float4 r;
            float v0 = acc[i][0] + bv;
            float v1 = acc[i][1] + bv;
            float v2 = acc[i][2] + bv;
            float v3 = acc[i][3] + bv;
            if (do_lrelu) {
                v0 = v0 >= 0.f ? v0 : 0.01f*v0;
                v1 = v1 >= 0.f ? v1 : 0.01f*v1;
                v2 = v2 >= 0.f ? v2 : 0.01f*v2;
                v3 = v3 >= 0.f ? v3 : 0.01f*v3;
            }
            r.x = v0; r.y = v1; r.z = v2; r.w = v3;
            *(float4*)&dst[o*PLANE + base] = r;
        }
    }
}

// -------- deformable conv + residual + lrelu, fused --------
// smem: sA(512f) sB(512f) sWt(6912f) sOff(6912i) sDec(1728us) = 62848 B
__global__ void __launch_bounds__(256)
deform_kernel(const float* __restrict__ x, const float* __restrict__ bd,
              const float* __restrict__ br, float* __restrict__ out)
{
    extern __shared__ char smraw[];
    float* sA  = (float*)smraw;                 // 8*64
    float* sB  = sA + 512;                      // 8*64
    float* sWt = sB + 512;                      // 27*64*4
    int*   sOff = (int*)(sWt + KTAP*64*4);      // 27*64*4
    unsigned short* sDec = (unsigned short*)(sOff + KTAP*64*4); // 1728

    int tid = threadIdx.x;
    int t = blockIdx.x >> 6;
    int h = blockIdx.x & 63;

    for (int e = tid; e < KTOT; e += 256) {
        int c = e / 27;
        int k = e - c*27;
        sDec[e] = (unsigned short)((c<<5) | k);
    }

    // precompute bilinear taps per (k, w): reused by all 64 channels
    for (int e = tid; e < KTAP*64; e += 256) {
        int k = e >> 6, w = e & 63;
        int kt = k / 9; int r = k - kt*9;
        int kh = r / 3; int kw = r - kh*3;
        int t_in = t - 1 + kt;
        bool t_ok = ((unsigned)t_in < TT);
        int t_c = min(max(t_in,0),TT-1);
        int pidx = t*HWX + h*WWD + w;
        float dh = g_off[(2*k)*PLANE + pidx];
        float dw = g_off[(2*k+1)*PLANE + pidx];
        float h_s = (float)(h - 1 + kh) + dh;
        float w_s = (float)(w - 1 + kw) + dw;
        float h0f = floorf(h_s), w0f = floorf(w_s);
        float fh = h_s - h0f,  fw = w_s - w0f;
        int h0 = (int)h0f, w0 = (int)w0f;
        int tb = t_c*HWX;
        #pragma unroll
        for (int q = 0; q < 4; q++) {
            int ih = h0 + (q >> 1), iw = w0 + (q & 1);
            bool ok = t_ok && ((unsigned)ih < HH) && ((unsigned)iw < WWD);
            int ihc = min(max(ih,0),HH-1), iwc = min(max(iw,0),WWD-1);
            float wh = (q >> 1) ? fh : 1.f - fh;
            float wv = (q & 1)  ? fw : 1.f - fw;
            sWt[e*4+q]  = ok ? wh*wv : 0.f;
            sOff[e*4+q] = tb + ihc*WWD + iwc;
        }
    }
    __syncthreads();

    int tx = tid & 15, ty = tid >> 4;
    float acc[4][4], acc2[4][4];
    #pragma unroll
    for (int i=0;i<4;i++)
        #pragma unroll
        for (int j=0;j<4;j++) { acc[i][j]=0.f; acc2[i][j]=0.f; }

    // main deformable GEMM: K = 1728
    for (int kk = 0; kk < KTOT; kk += 8) {
        #pragma unroll
        for (int i = 0; i < 2; i++) {
            int e = tid + i*256;
            int kc = e >> 6, o = e & 63;
            sA[kc*64 + o] = g_Wdt[(kk+kc)*64 + o];
        }
        #pragma unroll
        for (int i = 0; i < 2; i++) {
            int e = tid + i*256;
            int kc = e >> 6, w = e & 63;
            unsigned int d = sDec[kk+kc];
            int c = d >> 5;
            int k = d & 31;
            int ew = (k << 6) + w;
            const float* yc = g_y1 + c*PLANE;
            float4 wt4 = *(const float4*)&sWt[ew*4];
            int4  of4 = *(const int4*)&sOff[ew*4];
            float v = wt4.x*yc[of4.x] + wt4.y*yc[of4.y]
                    + wt4.z*yc[of4.z] + wt4.w*yc[of4.w];
            sB[kc*64 + w] = v;
        }
        __syncthreads();
        #pragma unroll
        for (int kc = 0; kc < 8; kc++) {
            float4 a = *(const float4*)&sA[kc*64 + ty*4];
            float4 b = *(const float4*)&sB[kc*64 + tx*4];
            float av[4] = {a.x,a.y,a.z,a.w};
            float bv[4] = {b.x,b.y,b.z,b.w};
            #pragma unroll
            for (int i=0;i<4;i++)
                #pragma unroll
                for (int j=0;j<4;j++)
                    acc[i][j] = fmaf(av[i], bv[j], acc[i][j]);
        }
        __syncthreads();
    }

    // residual 1x1 GEMM: K = 64
    int base_p = t*HWX + h*WWD;
    for (int kk = 0; kk < 64; kk += 8) {
        #pragma unroll
        for (int i = 0; i < 2; i++) {
            int e = tid + i*256;
            int kc = e >> 6, o = e & 63;
            sA[kc*64 + o] = g_Wrt[(kk+kc)*64 + o];
        }
        {
            int e = tid;             // 512 elems, 2 per thread
            int kc = e >> 6, w = e & 63;
            sB[kc*64 + w] = x[(kk+kc)*PLANE + base_p + w];
            e = tid + 256;
            kc = e >> 6; w = e & 63;
            sB[kc*64 + w] = x[(kk+kc)*PLANE + base_p + w];
        }
        __syncthreads();
        #pragma unroll
        for (int kc = 0; kc < 8; kc++) {
            float4 a = *(const float4*)&sA[kc*64 + ty*4];
            float4 b = *(const float4*)&sB[kc*64 + tx*4];
            float av[4] = {a.x,a.y,a.z,a.w};
            float bv[4] = {b.x,b.y,b.z,b.w};
            #pragma unroll
            for (int i=0;i<4;i++)
                #pragma unroll
                for (int j=0;j<4;j++)
                    acc2[i][j] = fmaf(av[i], bv[j], acc2[i][j]);
        }
        __syncthreads();
    }

    #pragma unroll
    for (int i=0;i<4;i++) {
        int o = ty*4 + i;
        float bdv = bd[o], brv = br[o];
        float4 r;
        float vj[4];
        #pragma unroll
        for (int j=0;j<4;j++) {
            float vd = acc[i][j] + bdv;
            vd = vd >= 0.f ? vd : 0.01f*vd;
            vj[j] = vd + acc2[i][j] + brv;
        }
        r.x = vj[0]; r.y = vj[1]; r.z = vj[2]; r.w = vj[3];
        *(float4*)&out[o*PLANE + base_p + tx*4] = r;
    }
}

// -------- launch --------
extern "C" void kernel_launch(void* const* d_in, const int* in_sizes, int n_in,
                              void* d_out, int out_size) {
    (void)in_sizes; (void)n_in; (void)out_size;
    const float* x    = (const float*)d_in[0];
    const float* W1   = (const float*)d_in[1];
    const float* b1   = (const float*)d_in[2];
    const float* Woff = (const float*)d_in[3];
    const float* boff = (const float*)d_in[4];
    const float* Wd   = (const float*)d_in[5];
    const float* bd   = (const float*)d_in[6];
    const float* Wr   = (const float*)d_in[7];
    const float* br   = (const float*)d_in[8];
    (void)Wd; (void)Wr;
    float* out = (float*)d_out;

    float *y1p, *offp, *W1tp, *Wofftp;
    cudaGetSymbolAddress((void**)&y1p, g_y1);
    cudaGetSymbolAddress((void**)&offp, g_off);
    cudaGetSymbolAddress((void**)&W1tp, g_W1t);
    cudaGetSymbolAddress((void**)&Wofftp, g_Wofft);

    const int SMEM_DEFORM = (512 + 512 + KTAP*64*4)*4 + KTAP*64*4*4 + KTOT*2; // 62848
    cudaFuncSetAttribute(deform_kernel, cudaFuncAttributeMaxDynamicSharedMemorySize, SMEM_DEFORM);

    prep_weights<<<(KTOT*64 + 255)/256, 256>>>(W1, Woff, d_in[5] ? (const float*)d_in[5] : Woff, (const float*)d_in[7]);
    conv3x3x3_kernel<<<512, 256>>>(x,   W1tp,   b1,   y1p,  64, 1);
    conv3x3x3_kernel<<<512, 256>>>(y1p, Wofftp, boff, offp, 54, 0);
    deform_kernel<<<512, 256, SMEM_DEFORM>>>(x, bd, br, out);
}